// round 6
// baseline (speedup 1.0000x reference)
#include <cuda_runtime.h>
#include <cstdint>
#include <math.h>

// RoI-Align FPN extractor, R6: double-buffered block-wide channel pipeline.
// feats lvl i: (2, 256, 200>>i, 336>>i) fp32, stride 4<<i.
// rois: (512,5). out: (512, 256, 7, 7) fp32.
//
// Grid: nroi*4 blocks (64-channel slices). Block: 256 thr. The block stages
// 4 channels at a time into one of two smem buffers via cp.async (all threads
// cooperate -> high MLP), while computing the previous 4 channels' 49 bins
// from the other buffer (thread t -> channel t/49, bin t%49; bin-invariant
// coefficients live in registers).

static constexpr int NS     = 14;    // OUT*SR samples per axis
static constexpr int NCH    = 256;
static constexpr int BUFN   = 1216;  // per-channel staging floats (worst ~1179)
static constexpr int CPS    = 4;     // channels per stage
static constexpr int NSTAGE = 16;    // 64 channels / 4
static constexpr int BINPAD = 52;

__device__ __forceinline__ void cp_async4(uint32_t dst_smem, const float* src)
{
    asm volatile("cp.async.ca.shared.global [%0], [%1], 4;\n"
                 :: "r"(dst_smem), "l"(src));
}
__device__ __forceinline__ void cp_commit()
{
    asm volatile("cp.async.commit_group;\n");
}
__device__ __forceinline__ void cp_wait1()
{
    asm volatile("cp.async.wait_group 1;\n" ::: "memory");
}
__device__ __forceinline__ void cp_wait0()
{
    asm volatile("cp.async.wait_group 0;\n" ::: "memory");
}

__global__ void __launch_bounds__(256, 5)
roi_align_fpn_kernel(const float* __restrict__ f0, const float* __restrict__ f1,
                     const float* __restrict__ f2, const float* __restrict__ f3,
                     const float* __restrict__ rois, float* __restrict__ out)
{
    __shared__ float s_wy0[NS], s_wy1[NS], s_wx0[NS], s_wx1[NS];
    __shared__ int   s_iy0[NS], s_iy1[NS], s_ix0[NS], s_ix1[NS];
    __shared__ int   s_lvl, s_b;
    __shared__ float2 s_cy[4][BINPAD];   // [tap][bin] = {row-offset bits, wy}
    __shared__ float2 s_cx[4][BINPAD];   // [tap][bin] = {col-offset bits, wx}
    __shared__ float  s_buf[2][CPS][BUFN];

    const int n     = blockIdx.x >> 2;
    const int slice = blockIdx.x & 3;
    const int tid   = threadIdx.x;

    if (tid == 0) {
        const float* r = rois + (size_t)n * 5;
        float rb = r[0], rx1 = r[1], ry1 = r[2], rx2 = r[3], ry2 = r[4];
        float sc = sqrtf((rx2 - rx1) * (ry2 - ry1));
        int lvl = (int)floor(log2((double)sc / 56.0 + 1e-6));
        lvl = lvl < 0 ? 0 : (lvl > 3 ? 3 : lvl);
        s_lvl = lvl;
        s_b   = (int)rb;
        const int H = 200 >> lvl, W = 336 >> lvl;
        const float isc = 1.0f / (float)(4 << lvl);
        float x1 = rx1 * isc - 0.5f, y1 = ry1 * isc - 0.5f;
        float x2 = rx2 * isc - 0.5f, y2 = ry2 * isc - 0.5f;
        float bw = (x2 - x1) / 7.0f, bh = (y2 - y1) / 7.0f;
#pragma unroll 1
        for (int i = 0; i < NS; i++) {
            float off = (float)(i >> 1) + ((float)(i & 1) + 0.5f) * 0.5f;
            {
                float c  = x1 + off * bw;
                float v  = (c >= -1.0f && c <= (float)W) ? 1.0f : 0.0f;
                float cc = fminf(fmaxf(c, 0.0f), (float)W - 1.0f);
                int lo   = (int)floorf(cc);
                int hi   = min(lo + 1, W - 1);
                float fr = cc - (float)lo;
                s_ix0[i] = lo; s_ix1[i] = hi;
                s_wx0[i] = v * (1.0f - fr); s_wx1[i] = v * fr;
            }
            {
                float c  = y1 + off * bh;
                float v  = (c >= -1.0f && c <= (float)H) ? 1.0f : 0.0f;
                float cc = fminf(fmaxf(c, 0.0f), (float)H - 1.0f);
                int lo   = (int)floorf(cc);
                int hi   = min(lo + 1, H - 1);
                float fr = cc - (float)lo;
                s_iy0[i] = lo; s_iy1[i] = hi;
                s_wy0[i] = v * (1.0f - fr); s_wy1[i] = v * fr;
            }
        }
    }
    __syncthreads();

    const int lvl = s_lvl, b = s_b;
    const int H = 200 >> lvl, W = 336 >> lvl;
    const int HW = H * W;
    const float* fb = (lvl == 0) ? f0 : (lvl == 1) ? f1 : (lvl == 2) ? f2 : f3;
    fb += ((size_t)b * NCH + slice * 64) * HW;     // base of this block's 64 ch

    const int ymin  = s_iy0[0];
    const int xmin  = s_ix0[0];
    const int rowsN = s_iy1[NS - 1] - ymin + 1;
    const int colsN = s_ix1[NS - 1] - xmin + 1;
    const int colsPad = colsN | 1;
    const bool useSmem = (rowsN * colsPad) <= BUFN;

    const int stride = useSmem ? colsPad : W;
    const int oy0    = useSmem ? ymin : 0;
    const int ox0    = useSmem ? xmin : 0;

    // Build per-bin coefficient tables (49 bins x 4 taps).
    if (tid < 196) {
        const int i   = tid / 49;
        const int bin = tid - i * 49;
        const int by  = bin / 7, bx = bin - by * 7;
        const int r   = 2 * by + (i >> 1);
        const int c   = 2 * bx + (i >> 1);
        int   iy = (i & 1) ? s_iy1[r] : s_iy0[r];
        float wy = (i & 1) ? s_wy1[r] : s_wy0[r];
        int   ix = (i & 1) ? s_ix1[c] : s_ix0[c];
        float wx = (i & 1) ? s_wx1[c] : s_wx0[c];
        s_cy[i][bin] = make_float2(__int_as_float((iy - oy0) * stride), wy);
        s_cx[i][bin] = make_float2(__int_as_float(ix - ox0), wx);
    }
    __syncthreads();

    // Hoist this thread's bin coefficients (bin fixed across all stages).
    const bool compute = tid < 196;
    const int  myBin   = compute ? (tid % 49) : 0;
    const int  myCh    = compute ? (tid / 49) : 0;    // channel within stage (0..3)
    int   offY[4], offX[4];
    float wY[4], wX[4];
#pragma unroll
    for (int i = 0; i < 4; i++) {
        float2 cy = s_cy[i][myBin];
        float2 cx = s_cx[i][myBin];
        offY[i] = __float_as_int(cy.x); wY[i] = cy.y;
        offX[i] = __float_as_int(cx.x); wX[i] = cx.y;
    }

    float* oBase = out + ((size_t)n * NCH + slice * 64) * 49;

    if (useSmem) {
        const unsigned umagic = 0xFFFFFFFFu / (unsigned)colsN + 1u;
        const int stageTot = rowsN * colsN;
        const uint32_t smbase = (uint32_t)__cvta_generic_to_shared(&s_buf[0][0][0]);

        // stage s -> buffer s&1: load channels s*4 .. s*4+3, all threads
        auto stage = [&](int s) {
            const uint32_t dst0 = smbase + (uint32_t)((s & 1) * CPS * BUFN) * 4u;
#pragma unroll 1
            for (int c = 0; c < CPS; c++) {
                const float* src = fb + (size_t)(s * CPS + c) * HW
                                      + (size_t)ymin * W + xmin;
                const uint32_t dst = dst0 + (uint32_t)(c * BUFN) * 4u;
                for (int i = tid; i < stageTot; i += 256) {
                    unsigned r = (unsigned)(((unsigned long long)i * umagic) >> 32);
                    int x = i - (int)r * colsN;
                    cp_async4(dst + 4u * ((int)r * colsPad + x), src + (int)r * W + x);
                }
            }
            cp_commit();
        };

        stage(0);
        stage(1);

#pragma unroll 1
        for (int s = 0; s < NSTAGE; s++) {
            if (s == NSTAGE - 1) cp_wait0(); else cp_wait1();
            __syncthreads();                       // buf[s&1] visible to all
            if (compute) {
                const float* base = &s_buf[s & 1][myCh][0];
                float acc = 0.0f;
#pragma unroll
                for (int i = 0; i < 4; i++) {
                    const float* rp = base + offY[i];
                    float ra = 0.0f;
#pragma unroll
                    for (int j = 0; j < 4; j++)
                        ra = fmaf(wX[j], rp[offX[j]], ra);
                    acc = fmaf(wY[i], ra, acc);
                }
                oBase[(size_t)s * (CPS * 49) + tid] = 0.25f * acc;
            }
            __syncthreads();                       // done reading buf[s&1]
            if (s + 2 < NSTAGE) stage(s + 2);      // overwrites buf[s&1]
        }
    } else {
        // rare fallback: region exceeds buffer -> direct gmem gathers
#pragma unroll 1
        for (int s = 0; s < NSTAGE; s++) {
            if (compute) {
                const float* src = fb + (size_t)(s * CPS + myCh) * HW;
                float acc = 0.0f;
#pragma unroll
                for (int i = 0; i < 4; i++) {
                    const float* rp = src + offY[i];
                    float ra = 0.0f;
#pragma unroll
                    for (int j = 0; j < 4; j++)
                        ra = fmaf(wX[j], __ldg(rp + offX[j]), ra);
                    acc = fmaf(wY[i], ra, acc);
                }
                oBase[(size_t)s * (CPS * 49) + tid] = 0.25f * acc;
            }
        }
    }
}

extern "C" void kernel_launch(void* const* d_in, const int* in_sizes, int n_in,
                              void* d_out, int out_size)
{
    const float* f0   = (const float*)d_in[0];
    const float* f1   = (const float*)d_in[1];
    const float* f2   = (const float*)d_in[2];
    const float* f3   = (const float*)d_in[3];
    const float* rois = (const float*)d_in[4];
    float* out = (float*)d_out;

    const int nroi = in_sizes[4] / 5;   // 512
    roi_align_fpn_kernel<<<nroi * 4, 256>>>(f0, f1, f2, f3, rois, out);
}